// round 15
// baseline (speedup 1.0000x reference)
#include <cuda_runtime.h>
#include <cuda_fp16.h>
#include <cuda_bf16.h>

#define N_NODES 100000
#define N_EDGES 1600000
#define F 64
#define NCLS 16
#define NEG_SLOPE 0.01f

#define SCAN_BLK 1024
#define SCAN_NB ((N_NODES + SCAN_BLK - 1) / SCAN_BLK)   // 98

#define EB4   ((N_EDGES / 4 + 255) / 256)   // 1563 edge blocks
#define NB128 ((N_NODES + 127) / 128)       // 782 GEMM blocks (128 rows each)
#define WSTRIDE 72                          // smem W stride for N=64 tiles

typedef unsigned long long ull;

// ---------------- scratch (device globals; zero at module load) --------------
__device__ int    g_deg[N_NODES];
__device__ int    g_off[N_NODES + 1];
__device__ int    g_rank[N_EDGES];       // per-edge rank within its dst segment
__device__ int    g_csr[N_EDGES];        // premultiplied: src * 8 (uint4-row offset)
__device__ int    g_scan_incl[SCAN_NB];
__device__ int    g_scan_flag[SCAN_NB];
__device__ __half g_P[(size_t)N_NODES * F];
__device__ __half g_Pl[(size_t)N_NODES * F];
__device__ __half g_H[(size_t)N_NODES * F];   // layer-1 output, fp16

// ---------------- helpers ----------------------------------------------------
__device__ __forceinline__ unsigned hmax2u(unsigned a, unsigned b) {
    __half2 r = __hmax2(*reinterpret_cast<__half2*>(&a),
                        *reinterpret_cast<__half2*>(&b));
    return *reinterpret_cast<unsigned*>(&r);
}
__device__ __forceinline__ unsigned f2tf32(float f) {
    unsigned u; asm("cvt.rna.tf32.f32 %0, %1;" : "=r"(u) : "f"(f)); return u;
}
__device__ __forceinline__ unsigned ldg_tf32(const float* p) {
    return f2tf32(__ldg(p));
}
__device__ __forceinline__ unsigned ldg_tf32(const __half* p) {
    return f2tf32(__half2float(__ldg(p)));
}
__device__ __forceinline__ void mma_tf32(float* d, const unsigned* a,
                                         unsigned b0, unsigned b1) {
    asm volatile(
        "mma.sync.aligned.m16n8k8.row.col.f32.tf32.tf32.f32 "
        "{%0,%1,%2,%3}, {%4,%5,%6,%7}, {%8,%9}, {%0,%1,%2,%3};"
        : "+f"(d[0]), "+f"(d[1]), "+f"(d[2]), "+f"(d[3])
        : "r"(a[0]), "r"(a[1]), "r"(a[2]), "r"(a[3]), "r"(b0), "r"(b1));
}

// ---- tf32 pool GEMM body: 16 rows per warp (128/block) ----------------------
// P = relu(X @ W + b) -> fp16. TX = float or __half.
template <typename TX>
__device__ __forceinline__ void gemm_pool_tf32_body(
        const TX* __restrict__ X, const unsigned* __restrict__ sWt,
        const float* __restrict__ sbias, __half* __restrict__ Y, int rowbase) {
    int lane = threadIdx.x & 31;
    int warp = threadIdx.x >> 5;
    int g = lane >> 2;
    int t4 = lane & 3;
    int wbase = rowbase + warp * 16;
    const int NMAX = N_NODES - 1;

    int ra = min(wbase + g,     NMAX);
    int rb = min(wbase + g + 8, NMAX);

    float acc[8][4];
    #pragma unroll
    for (int nf = 0; nf < 8; nf++) {
        float bb0 = sbias[8 * nf + 2 * t4];
        float bb1 = sbias[8 * nf + 2 * t4 + 1];
        acc[nf][0] = bb0; acc[nf][1] = bb1;
        acc[nf][2] = bb0; acc[nf][3] = bb1;
    }

    #pragma unroll
    for (int kf = 0; kf < 8; kf++) {
        int k0 = 8 * kf + t4;
        unsigned a[4];
        a[0] = ldg_tf32(&X[(size_t)ra * F + k0]);
        a[1] = ldg_tf32(&X[(size_t)rb * F + k0]);
        a[2] = ldg_tf32(&X[(size_t)ra * F + k0 + 4]);
        a[3] = ldg_tf32(&X[(size_t)rb * F + k0 + 4]);
        #pragma unroll
        for (int nf = 0; nf < 8; nf++) {
            unsigned b0 = sWt[(8 * kf + t4) * WSTRIDE + 8 * nf + g];
            unsigned b1 = sWt[(8 * kf + t4 + 4) * WSTRIDE + 8 * nf + g];
            mma_tf32(acc[nf], a, b0, b1);
        }
    }

    int sa = wbase + g, sb = sa + 8;
    #pragma unroll
    for (int nf = 0; nf < 8; nf++) {
        int col = 8 * nf + 2 * t4;
        if (sa < N_NODES) {
            __half2 h = __floats2half2_rn(fmaxf(acc[nf][0], 0.f),
                                          fmaxf(acc[nf][1], 0.f));
            *(__half2*)(Y + (size_t)sa * F + col) = h;
        }
        if (sb < N_NODES) {
            __half2 h = __floats2half2_rn(fmaxf(acc[nf][2], 0.f),
                                          fmaxf(acc[nf][3], 0.f));
            *(__half2*)(Y + (size_t)sb * F + col) = h;
        }
    }
}

__device__ __forceinline__ void stage_w_tf32(
        const float* __restrict__ W, const float* __restrict__ b,
        unsigned* sWt, float* sbias) {
    int t = threadIdx.x;
    for (int i = t; i < F * F; i += 256) {
        int k = i >> 6, n = i & 63;
        sWt[k * WSTRIDE + n] = f2tf32(__ldg(&W[i]));
    }
    if (t < F) sbias[t] = b[t];
}

// ------- K1: merged edge histogram (rank-recording) + layer-1 GEMM -----------
__global__ __launch_bounds__(256) void hist_gemm_kernel(
        const int4* __restrict__ dst4,
        const float* __restrict__ X, const float* __restrict__ W,
        const float* __restrict__ b, __half* __restrict__ Y) {
    __shared__ unsigned sWt[F * WSTRIDE];
    __shared__ float sbias[F];
    int t = threadIdx.x;

    if (blockIdx.x < EB4) {
        if (blockIdx.x == 0 && t < SCAN_NB) g_scan_flag[t] = 0;
        int i = blockIdx.x * 256 + t;
        if (i < N_EDGES / 4) {
            int4 d = __ldg(&dst4[i]);
            int r0 = atomicAdd(&g_deg[d.x], 1);
            int r1 = atomicAdd(&g_deg[d.y], 1);
            int r2 = atomicAdd(&g_deg[d.z], 1);
            int r3 = atomicAdd(&g_deg[d.w], 1);
            int4 rk; rk.x = r0; rk.y = r1; rk.z = r2; rk.w = r3;
            ((int4*)g_rank)[i] = rk;
        }
        return;
    }

    stage_w_tf32(W, b, sWt, sbias);
    __syncthreads();
    gemm_pool_tf32_body(X, sWt, sbias, Y, (blockIdx.x - EB4) * 128);
}

// ---------------- layer-2 pool GEMM (tf32, fp16 input H) ---------------------
__global__ __launch_bounds__(256) void gemm_pool_kernel(
        const __half* __restrict__ X, const float* __restrict__ W,
        const float* __restrict__ b, __half* __restrict__ Y) {
    __shared__ unsigned sWt[F * WSTRIDE];
    __shared__ float sbias[F];
    stage_w_tf32(W, b, sWt, sbias);
    __syncthreads();
    gemm_pool_tf32_body(X, sWt, sbias, Y, blockIdx.x * 128);
}

// ------- single-kernel scan: decoupled lookback ------------------------------
__global__ __launch_bounds__(SCAN_BLK) void scan_kernel() {
    __shared__ int s[SCAN_BLK];
    __shared__ int s_carry;
    int t = threadIdx.x;
    int b = blockIdx.x;
    int idx = b * SCAN_BLK + t;
    int val = 0;
    if (idx < N_NODES) { val = g_deg[idx]; g_deg[idx] = 0; }
    s[t] = val;
    __syncthreads();
    #pragma unroll
    for (int o = 1; o < SCAN_BLK; o <<= 1) {
        int x = (t >= o) ? s[t - o] : 0;
        __syncthreads();
        s[t] += x;
        __syncthreads();
    }
    int incl = s[t];
    if (t == SCAN_BLK - 1) {
        g_scan_incl[b] = incl;
        __threadfence();
        atomicExch(&g_scan_flag[b], 1);
    }
    if (t < 32) {
        int c = 0;
        for (int i = t; i < b; i += 32) {
            while (atomicAdd(&g_scan_flag[i], 0) == 0) { __nanosleep(40); }
            __threadfence();
            c += g_scan_incl[i];
        }
        #pragma unroll
        for (int o = 16; o; o >>= 1) c += __shfl_down_sync(0xffffffff, c, o);
        if (t == 0) s_carry = c;
    }
    __syncthreads();
    int off = s_carry + incl - val;
    if (idx < N_NODES) g_off[idx] = off;
    if (idx == 0) g_off[N_NODES] = N_EDGES;
}

// ------- CSR fill, atomic-free (premultiplied entries) -----------------------
__global__ void fill_csr_kernel(const int4* __restrict__ src4,
                                const int4* __restrict__ dst4) {
    int i = blockIdx.x * blockDim.x + threadIdx.x;
    if (i < N_EDGES / 4) {
        int4 s = __ldg(&src4[i]);
        int4 d = __ldg(&dst4[i]);
        int4 r = ((const int4*)g_rank)[i];
        g_csr[g_off[d.x] + r.x] = s.x * 8;
        g_csr[g_off[d.y] + r.y] = s.y * 8;
        g_csr[g_off[d.z] + r.z] = s.z * 8;
        g_csr[g_off[d.w] + r.w] = s.w * 8;
    }
}

// ------- segment max pool: 8-lane group per node, 4 nodes/warp, unroll 8 -----
// launch_bounds(256, 6): cap regs at ~42 to reach 6 CTAs/SM (48 warps)
__global__ __launch_bounds__(256, 6) void pool_kernel(
        const __half* __restrict__ P, __half* __restrict__ Pl) {
    int warp_g = (blockIdx.x * 256 + threadIdx.x) >> 5;
    int lane   = threadIdx.x & 31;
    int grp = lane >> 3;
    int sub = lane & 7;
    int node = warp_g * 4 + grp;
    if (node >= N_NODES) return;

    int s0 = g_off[node];
    int s1 = g_off[node + 1];
    unsigned m0 = 0, m1 = 0, m2 = 0, m3 = 0;
    const uint4* Prow = (const uint4*)P;

    if (s0 < s1) {
        int last = s1 - 1;
        for (int e = s0; e < s1; e += 8) {
            int idx[8];
            #pragma unroll
            for (int q = 0; q < 8; q++) idx[q] = g_csr[min(e + q, last)];
            uint4 v[8];
            #pragma unroll
            for (int q = 0; q < 8; q++) v[q] = __ldg(&Prow[idx[q] + sub]);
            unsigned a0 = hmax2u(hmax2u(v[0].x, v[1].x), hmax2u(v[2].x, v[3].x));
            unsigned b0 = hmax2u(hmax2u(v[4].x, v[5].x), hmax2u(v[6].x, v[7].x));
            unsigned a1 = hmax2u(hmax2u(v[0].y, v[1].y), hmax2u(v[2].y, v[3].y));
            unsigned b1 = hmax2u(hmax2u(v[4].y, v[5].y), hmax2u(v[6].y, v[7].y));
            unsigned a2 = hmax2u(hmax2u(v[0].z, v[1].z), hmax2u(v[2].z, v[3].z));
            unsigned b2 = hmax2u(hmax2u(v[4].z, v[5].z), hmax2u(v[6].z, v[7].z));
            unsigned a3 = hmax2u(hmax2u(v[0].w, v[1].w), hmax2u(v[2].w, v[3].w));
            unsigned b3 = hmax2u(hmax2u(v[4].w, v[5].w), hmax2u(v[6].w, v[7].w));
            m0 = hmax2u(m0, hmax2u(a0, b0));
            m1 = hmax2u(m1, hmax2u(a1, b1));
            m2 = hmax2u(m2, hmax2u(a2, b2));
            m3 = hmax2u(m3, hmax2u(a3, b3));
        }
    }
    uint4 o; o.x = m0; o.y = m1; o.z = m2; o.w = m3;
    ((uint4*)(Pl + (size_t)node * F))[sub] = o;
}

// ------- tf32 out-GEMM: 16 rows/warp, Y = act([X | PL] @ [Ws;Wn] + b) --------
// TX: float or __half input; TY: float or __half output
template <int DOUT, int ACT, int SW, typename TX, typename TY>
__device__ __forceinline__ void gemm_out_tf32_body(
        const TX* __restrict__ X, const __half* __restrict__ PL,
        const unsigned* __restrict__ sWt, const float* __restrict__ sbias,
        TY* __restrict__ Y, int rowbase) {
    const int NF = DOUT / 8;
    int lane = threadIdx.x & 31;
    int warp = threadIdx.x >> 5;
    int g = lane >> 2;
    int t4 = lane & 3;
    int wbase = rowbase + warp * 16;
    const int NMAX = N_NODES - 1;

    int ra = min(wbase + g,     NMAX);
    int rb = min(wbase + g + 8, NMAX);

    float acc[NF][4];
    #pragma unroll
    for (int nf = 0; nf < NF; nf++) {
        float bb0 = sbias[8 * nf + 2 * t4];
        float bb1 = sbias[8 * nf + 2 * t4 + 1];
        acc[nf][0] = bb0; acc[nf][1] = bb1;
        acc[nf][2] = bb0; acc[nf][3] = bb1;
    }

    // self term: kf 0..7 from X
    #pragma unroll
    for (int kf = 0; kf < 8; kf++) {
        int k0 = 8 * kf + t4;
        unsigned a[4];
        a[0] = ldg_tf32(&X[(size_t)ra * F + k0]);
        a[1] = ldg_tf32(&X[(size_t)rb * F + k0]);
        a[2] = ldg_tf32(&X[(size_t)ra * F + k0 + 4]);
        a[3] = ldg_tf32(&X[(size_t)rb * F + k0 + 4]);
        #pragma unroll
        for (int nf = 0; nf < NF; nf++) {
            unsigned b0 = sWt[(8 * kf + t4) * SW + 8 * nf + g];
            unsigned b1 = sWt[(8 * kf + t4 + 4) * SW + 8 * nf + g];
            mma_tf32(acc[nf], a, b0, b1);
        }
    }
    // neighbor term: kf 8..15 from PL (fp16)
    #pragma unroll
    for (int kf = 0; kf < 8; kf++) {
        int k0 = 8 * kf + t4;
        unsigned a[4];
        a[0] = ldg_tf32(&PL[(size_t)ra * F + k0]);
        a[1] = ldg_tf32(&PL[(size_t)rb * F + k0]);
        a[2] = ldg_tf32(&PL[(size_t)ra * F + k0 + 4]);
        a[3] = ldg_tf32(&PL[(size_t)rb * F + k0 + 4]);
        #pragma unroll
        for (int nf = 0; nf < NF; nf++) {
            unsigned b0 = sWt[(64 + 8 * kf + t4) * SW + 8 * nf + g];
            unsigned b1 = sWt[(64 + 8 * kf + t4 + 4) * SW + 8 * nf + g];
            mma_tf32(acc[nf], a, b0, b1);
        }
    }

    int sa = wbase + g, sb = sa + 8;
    #pragma unroll
    for (int nf = 0; nf < NF; nf++) {
        int col = 8 * nf + 2 * t4;
        float v0 = acc[nf][0], v1 = acc[nf][1];
        float v2 = acc[nf][2], v3 = acc[nf][3];
        if (ACT == 1) {
            v0 = (v0 >= 0.f) ? v0 : NEG_SLOPE * v0;
            v1 = (v1 >= 0.f) ? v1 : NEG_SLOPE * v1;
            v2 = (v2 >= 0.f) ? v2 : NEG_SLOPE * v2;
            v3 = (v3 >= 0.f) ? v3 : NEG_SLOPE * v3;
        }
        if (sizeof(TY) == 2) {
            if (sa < N_NODES) {
                __half2 h = __floats2half2_rn(v0, v1);
                *(__half2*)((__half*)Y + (size_t)sa * DOUT + col) = h;
            }
            if (sb < N_NODES) {
                __half2 h = __floats2half2_rn(v2, v3);
                *(__half2*)((__half*)Y + (size_t)sb * DOUT + col) = h;
            }
        } else {
            if (sa < N_NODES) {
                float2 o; o.x = v0; o.y = v1;
                *(float2*)((float*)Y + (size_t)sa * DOUT + col) = o;
            }
            if (sb < N_NODES) {
                float2 o; o.x = v2; o.y = v3;
                *(float2*)((float*)Y + (size_t)sb * DOUT + col) = o;
            }
        }
    }
}

template <int DOUT, int SW>
__device__ __forceinline__ void stage_w2_tf32(
        const float* __restrict__ Ws, const float* __restrict__ Wn,
        const float* __restrict__ b, unsigned* sWt, float* sbias) {
    int t = threadIdx.x;
    for (int i = t; i < F * DOUT; i += 256) {
        int k = i / DOUT, n = i % DOUT;
        sWt[k * SW + n]        = f2tf32(__ldg(&Ws[i]));
        sWt[(64 + k) * SW + n] = f2tf32(__ldg(&Wn[i]));
    }
    if (t < DOUT) sbias[t] = b[t];
}

template <int DOUT, int ACT, int SW, typename TX, typename TY>
__global__ __launch_bounds__(256) void gemm_out_kernel(
        const TX* __restrict__ X, const __half* __restrict__ PL,
        const float* __restrict__ Ws, const float* __restrict__ Wn,
        const float* __restrict__ b, TY* __restrict__ Y) {
    __shared__ unsigned sWt[128 * SW];
    __shared__ float sbias[DOUT];
    stage_w2_tf32<DOUT, SW>(Ws, Wn, b, sWt, sbias);
    __syncthreads();
    gemm_out_tf32_body<DOUT, ACT, SW>(X, PL, sWt, sbias, Y, blockIdx.x * 128);
}

// ---------------- launch -----------------------------------------------------
extern "C" void kernel_launch(void* const* d_in, const int* in_sizes, int n_in,
                              void* d_out, int out_size) {
    const float* in_feat = (const float*)d_in[0];
    const int*   src     = (const int*)d_in[1];
    const int*   dst     = (const int*)d_in[2];
    const float* W_pool1 = (const float*)d_in[3];
    const float* b_pool1 = (const float*)d_in[4];
    const float* W_self1 = (const float*)d_in[5];
    const float* W_neigh1= (const float*)d_in[6];
    const float* bias1   = (const float*)d_in[7];
    const float* W_pool2 = (const float*)d_in[8];
    const float* b_pool2 = (const float*)d_in[9];
    const float* W_self2 = (const float*)d_in[10];
    const float* W_neigh2= (const float*)d_in[11];
    const float* bias2   = (const float*)d_in[12];
    float* out = (float*)d_out;

    __half *dP, *dPl, *dH;
    cudaGetSymbolAddress((void**)&dP, g_P);
    cudaGetSymbolAddress((void**)&dPl, g_Pl);
    cudaGetSymbolAddress((void**)&dH, g_H);

    const int POOL_WARPS = (N_NODES + 3) / 4;
    const int POOLB = (POOL_WARPS * 32 + 255) / 256;

    // K1: flag reset + rank-recording histogram + layer-1 pool GEMM (tf32)
    hist_gemm_kernel<<<EB4 + NB128, 256>>>((const int4*)dst,
                                           in_feat, W_pool1, b_pool1, dP);
    // K2: single-pass scan (offsets only)
    scan_kernel<<<SCAN_NB, SCAN_BLK>>>();
    // K3: atomic-free CSR fill (premultiplied entries)
    fill_csr_kernel<<<EB4, 256>>>((const int4*)src, (const int4*)dst);
    // K4: layer-1 pool
    pool_kernel<<<POOLB, 256>>>(dP, dPl);
    // K5: H(fp16) = leaky(X@Ws1 + Pl@Wn1 + b1)  (tf32, K=128)
    gemm_out_kernel<64, 1, 72><<<NB128, 256>>>(in_feat, dPl, W_self1, W_neigh1,
                                               bias1, dH);
    // K6: P = relu(H@Wp2 + bp2)  (tf32, fp16 input)
    gemm_pool_kernel<<<NB128, 256>>>(dH, W_pool2, b_pool2, dP);
    // K7: layer-2 pool
    pool_kernel<<<POOLB, 256>>>(dP, dPl);
    // K8: out(fp32) = H@Ws2 + Pl@Wn2 + b2  (tf32, K=128, fp16 input)
    gemm_out_kernel<16, 0, 24><<<NB128, 256>>>(dH, dPl, W_self2, W_neigh2,
                                               bias2, out);
}

// round 16
// speedup vs baseline: 1.0163x; 1.0163x over previous
#include <cuda_runtime.h>
#include <cuda_fp16.h>
#include <cuda_bf16.h>

#define N_NODES 100000
#define N_EDGES 1600000
#define F 64
#define NCLS 16
#define NEG_SLOPE 0.01f

#define SCAN_BLK 1024
#define SCAN_NB ((N_NODES + SCAN_BLK - 1) / SCAN_BLK)   // 98

#define EB4   ((N_EDGES / 4 + 255) / 256)   // 1563 edge blocks
#define NB128 ((N_NODES + 127) / 128)       // 782 GEMM blocks (128 rows each)
#define WSTRIDE 72                          // smem W stride for N=64 tiles

typedef unsigned long long ull;

// ---------------- scratch (device globals; zero at module load) --------------
__device__ int    g_deg[N_NODES];
__device__ int    g_off[N_NODES + 1];
__device__ int    g_rank[N_EDGES];       // per-edge rank within its dst segment
__device__ int    g_csr[N_EDGES];        // premultiplied: src * 8 (uint4-row offset)
__device__ int    g_scan_incl[SCAN_NB];
__device__ int    g_scan_flag[SCAN_NB];
__device__ __half g_P[(size_t)N_NODES * F];
__device__ __half g_Pl[(size_t)N_NODES * F];
__device__ __half g_H[(size_t)N_NODES * F];   // layer-1 output, fp16

// ---------------- helpers ----------------------------------------------------
__device__ __forceinline__ unsigned hmax2u(unsigned a, unsigned b) {
    __half2 r = __hmax2(*reinterpret_cast<__half2*>(&a),
                        *reinterpret_cast<__half2*>(&b));
    return *reinterpret_cast<unsigned*>(&r);
}
__device__ __forceinline__ unsigned f2tf32(float f) {
    unsigned u; asm("cvt.rna.tf32.f32 %0, %1;" : "=r"(u) : "f"(f)); return u;
}
__device__ __forceinline__ unsigned ldg_tf32(const float* p) {
    return f2tf32(__ldg(p));
}
__device__ __forceinline__ unsigned ldg_tf32(const __half* p) {
    return f2tf32(__half2float(__ldg(p)));
}
__device__ __forceinline__ void mma_tf32(float* d, const unsigned* a,
                                         unsigned b0, unsigned b1) {
    asm volatile(
        "mma.sync.aligned.m16n8k8.row.col.f32.tf32.tf32.f32 "
        "{%0,%1,%2,%3}, {%4,%5,%6,%7}, {%8,%9}, {%0,%1,%2,%3};"
        : "+f"(d[0]), "+f"(d[1]), "+f"(d[2]), "+f"(d[3])
        : "r"(a[0]), "r"(a[1]), "r"(a[2]), "r"(a[3]), "r"(b0), "r"(b1));
}

// ---- tf32 pool GEMM body: 16 rows per warp (128/block) ----------------------
// P = relu(X @ W + b) -> fp16. TX = float or __half.
template <typename TX>
__device__ __forceinline__ void gemm_pool_tf32_body(
        const TX* __restrict__ X, const unsigned* __restrict__ sWt,
        const float* __restrict__ sbias, __half* __restrict__ Y, int rowbase) {
    int lane = threadIdx.x & 31;
    int warp = threadIdx.x >> 5;
    int g = lane >> 2;
    int t4 = lane & 3;
    int wbase = rowbase + warp * 16;
    const int NMAX = N_NODES - 1;

    int ra = min(wbase + g,     NMAX);
    int rb = min(wbase + g + 8, NMAX);

    float acc[8][4];
    #pragma unroll
    for (int nf = 0; nf < 8; nf++) {
        float bb0 = sbias[8 * nf + 2 * t4];
        float bb1 = sbias[8 * nf + 2 * t4 + 1];
        acc[nf][0] = bb0; acc[nf][1] = bb1;
        acc[nf][2] = bb0; acc[nf][3] = bb1;
    }

    #pragma unroll
    for (int kf = 0; kf < 8; kf++) {
        int k0 = 8 * kf + t4;
        unsigned a[4];
        a[0] = ldg_tf32(&X[(size_t)ra * F + k0]);
        a[1] = ldg_tf32(&X[(size_t)rb * F + k0]);
        a[2] = ldg_tf32(&X[(size_t)ra * F + k0 + 4]);
        a[3] = ldg_tf32(&X[(size_t)rb * F + k0 + 4]);
        #pragma unroll
        for (int nf = 0; nf < 8; nf++) {
            unsigned b0 = sWt[(8 * kf + t4) * WSTRIDE + 8 * nf + g];
            unsigned b1 = sWt[(8 * kf + t4 + 4) * WSTRIDE + 8 * nf + g];
            mma_tf32(acc[nf], a, b0, b1);
        }
    }

    int sa = wbase + g, sb = sa + 8;
    #pragma unroll
    for (int nf = 0; nf < 8; nf++) {
        int col = 8 * nf + 2 * t4;
        if (sa < N_NODES) {
            __half2 h = __floats2half2_rn(fmaxf(acc[nf][0], 0.f),
                                          fmaxf(acc[nf][1], 0.f));
            *(__half2*)(Y + (size_t)sa * F + col) = h;
        }
        if (sb < N_NODES) {
            __half2 h = __floats2half2_rn(fmaxf(acc[nf][2], 0.f),
                                          fmaxf(acc[nf][3], 0.f));
            *(__half2*)(Y + (size_t)sb * F + col) = h;
        }
    }
}

__device__ __forceinline__ void stage_w_tf32(
        const float* __restrict__ W, const float* __restrict__ b,
        unsigned* sWt, float* sbias) {
    int t = threadIdx.x;
    for (int i = t; i < F * F; i += 256) {
        int k = i >> 6, n = i & 63;
        sWt[k * WSTRIDE + n] = f2tf32(__ldg(&W[i]));
    }
    if (t < F) sbias[t] = b[t];
}

// ------- K1: merged edge histogram (rank-recording) + layer-1 GEMM -----------
__global__ __launch_bounds__(256) void hist_gemm_kernel(
        const int4* __restrict__ dst4,
        const float* __restrict__ X, const float* __restrict__ W,
        const float* __restrict__ b, __half* __restrict__ Y) {
    __shared__ unsigned sWt[F * WSTRIDE];
    __shared__ float sbias[F];
    int t = threadIdx.x;

    if (blockIdx.x < EB4) {
        if (blockIdx.x == 0 && t < SCAN_NB) g_scan_flag[t] = 0;
        int i = blockIdx.x * 256 + t;
        if (i < N_EDGES / 4) {
            int4 d = __ldg(&dst4[i]);
            int r0 = atomicAdd(&g_deg[d.x], 1);
            int r1 = atomicAdd(&g_deg[d.y], 1);
            int r2 = atomicAdd(&g_deg[d.z], 1);
            int r3 = atomicAdd(&g_deg[d.w], 1);
            int4 rk; rk.x = r0; rk.y = r1; rk.z = r2; rk.w = r3;
            ((int4*)g_rank)[i] = rk;
        }
        return;
    }

    stage_w_tf32(W, b, sWt, sbias);
    __syncthreads();
    gemm_pool_tf32_body(X, sWt, sbias, Y, (blockIdx.x - EB4) * 128);
}

// ---------------- layer-2 pool GEMM (tf32, fp16 input H) ---------------------
__global__ __launch_bounds__(256) void gemm_pool_kernel(
        const __half* __restrict__ X, const float* __restrict__ W,
        const float* __restrict__ b, __half* __restrict__ Y) {
    __shared__ unsigned sWt[F * WSTRIDE];
    __shared__ float sbias[F];
    stage_w_tf32(W, b, sWt, sbias);
    __syncthreads();
    gemm_pool_tf32_body(X, sWt, sbias, Y, blockIdx.x * 128);
}

// ------- single-kernel scan: decoupled lookback ------------------------------
__global__ __launch_bounds__(SCAN_BLK) void scan_kernel() {
    __shared__ int s[SCAN_BLK];
    __shared__ int s_carry;
    int t = threadIdx.x;
    int b = blockIdx.x;
    int idx = b * SCAN_BLK + t;
    int val = 0;
    if (idx < N_NODES) { val = g_deg[idx]; g_deg[idx] = 0; }
    s[t] = val;
    __syncthreads();
    #pragma unroll
    for (int o = 1; o < SCAN_BLK; o <<= 1) {
        int x = (t >= o) ? s[t - o] : 0;
        __syncthreads();
        s[t] += x;
        __syncthreads();
    }
    int incl = s[t];
    if (t == SCAN_BLK - 1) {
        g_scan_incl[b] = incl;
        __threadfence();
        atomicExch(&g_scan_flag[b], 1);
    }
    if (t < 32) {
        int c = 0;
        for (int i = t; i < b; i += 32) {
            while (atomicAdd(&g_scan_flag[i], 0) == 0) { __nanosleep(40); }
            __threadfence();
            c += g_scan_incl[i];
        }
        #pragma unroll
        for (int o = 16; o; o >>= 1) c += __shfl_down_sync(0xffffffff, c, o);
        if (t == 0) s_carry = c;
    }
    __syncthreads();
    int off = s_carry + incl - val;
    if (idx < N_NODES) g_off[idx] = off;
    if (idx == 0) g_off[N_NODES] = N_EDGES;
}

// ------- CSR fill, atomic-free (premultiplied entries) -----------------------
__global__ void fill_csr_kernel(const int4* __restrict__ src4,
                                const int4* __restrict__ dst4) {
    int i = blockIdx.x * blockDim.x + threadIdx.x;
    if (i < N_EDGES / 4) {
        int4 s = __ldg(&src4[i]);
        int4 d = __ldg(&dst4[i]);
        int4 r = ((const int4*)g_rank)[i];
        g_csr[g_off[d.x] + r.x] = s.x * 8;
        g_csr[g_off[d.y] + r.y] = s.y * 8;
        g_csr[g_off[d.z] + r.z] = s.z * 8;
        g_csr[g_off[d.w] + r.w] = s.w * 8;
    }
}

// ------- segment max pool: 8-lane group per node, 4 nodes/warp, unroll 8 -----
__global__ __launch_bounds__(256) void pool_kernel(
        const __half* __restrict__ P, __half* __restrict__ Pl) {
    int warp_g = (blockIdx.x * 256 + threadIdx.x) >> 5;
    int lane   = threadIdx.x & 31;
    int grp = lane >> 3;
    int sub = lane & 7;
    int node = warp_g * 4 + grp;
    if (node >= N_NODES) return;

    int s0 = g_off[node];
    int s1 = g_off[node + 1];
    unsigned m0 = 0, m1 = 0, m2 = 0, m3 = 0;
    const uint4* Prow = (const uint4*)P;

    if (s0 < s1) {
        int last = s1 - 1;
        for (int e = s0; e < s1; e += 8) {
            int idx[8];
            #pragma unroll
            for (int q = 0; q < 8; q++) idx[q] = g_csr[min(e + q, last)];
            uint4 v[8];
            #pragma unroll
            for (int q = 0; q < 8; q++) v[q] = __ldg(&Prow[idx[q] + sub]);
            unsigned a0 = hmax2u(hmax2u(v[0].x, v[1].x), hmax2u(v[2].x, v[3].x));
            unsigned b0 = hmax2u(hmax2u(v[4].x, v[5].x), hmax2u(v[6].x, v[7].x));
            unsigned a1 = hmax2u(hmax2u(v[0].y, v[1].y), hmax2u(v[2].y, v[3].y));
            unsigned b1 = hmax2u(hmax2u(v[4].y, v[5].y), hmax2u(v[6].y, v[7].y));
            unsigned a2 = hmax2u(hmax2u(v[0].z, v[1].z), hmax2u(v[2].z, v[3].z));
            unsigned b2 = hmax2u(hmax2u(v[4].z, v[5].z), hmax2u(v[6].z, v[7].z));
            unsigned a3 = hmax2u(hmax2u(v[0].w, v[1].w), hmax2u(v[2].w, v[3].w));
            unsigned b3 = hmax2u(hmax2u(v[4].w, v[5].w), hmax2u(v[6].w, v[7].w));
            m0 = hmax2u(m0, hmax2u(a0, b0));
            m1 = hmax2u(m1, hmax2u(a1, b1));
            m2 = hmax2u(m2, hmax2u(a2, b2));
            m3 = hmax2u(m3, hmax2u(a3, b3));
        }
    }
    uint4 o; o.x = m0; o.y = m1; o.z = m2; o.w = m3;
    ((uint4*)(Pl + (size_t)node * F))[sub] = o;
}

// ------- tf32 out-GEMM: 16 rows/warp, Y = act([X | PL] @ [Ws;Wn] + b) --------
// TX: float or __half input; TY: float or __half output
template <int DOUT, int ACT, int SW, typename TX, typename TY>
__device__ __forceinline__ void gemm_out_tf32_body(
        const TX* __restrict__ X, const __half* __restrict__ PL,
        const unsigned* __restrict__ sWt, const float* __restrict__ sbias,
        TY* __restrict__ Y, int rowbase) {
    const int NF = DOUT / 8;
    int lane = threadIdx.x & 31;
    int warp = threadIdx.x >> 5;
    int g = lane >> 2;
    int t4 = lane & 3;
    int wbase = rowbase + warp * 16;
    const int NMAX = N_NODES - 1;

    int ra = min(wbase + g,     NMAX);
    int rb = min(wbase + g + 8, NMAX);

    float acc[NF][4];
    #pragma unroll
    for (int nf = 0; nf < NF; nf++) {
        float bb0 = sbias[8 * nf + 2 * t4];
        float bb1 = sbias[8 * nf + 2 * t4 + 1];
        acc[nf][0] = bb0; acc[nf][1] = bb1;
        acc[nf][2] = bb0; acc[nf][3] = bb1;
    }

    // self term: kf 0..7 from X
    #pragma unroll
    for (int kf = 0; kf < 8; kf++) {
        int k0 = 8 * kf + t4;
        unsigned a[4];
        a[0] = ldg_tf32(&X[(size_t)ra * F + k0]);
        a[1] = ldg_tf32(&X[(size_t)rb * F + k0]);
        a[2] = ldg_tf32(&X[(size_t)ra * F + k0 + 4]);
        a[3] = ldg_tf32(&X[(size_t)rb * F + k0 + 4]);
        #pragma unroll
        for (int nf = 0; nf < NF; nf++) {
            unsigned b0 = sWt[(8 * kf + t4) * SW + 8 * nf + g];
            unsigned b1 = sWt[(8 * kf + t4 + 4) * SW + 8 * nf + g];
            mma_tf32(acc[nf], a, b0, b1);
        }
    }
    // neighbor term: kf 8..15 from PL (fp16)
    #pragma unroll
    for (int kf = 0; kf < 8; kf++) {
        int k0 = 8 * kf + t4;
        unsigned a[4];
        a[0] = ldg_tf32(&PL[(size_t)ra * F + k0]);
        a[1] = ldg_tf32(&PL[(size_t)rb * F + k0]);
        a[2] = ldg_tf32(&PL[(size_t)ra * F + k0 + 4]);
        a[3] = ldg_tf32(&PL[(size_t)rb * F + k0 + 4]);
        #pragma unroll
        for (int nf = 0; nf < NF; nf++) {
            unsigned b0 = sWt[(64 + 8 * kf + t4) * SW + 8 * nf + g];
            unsigned b1 = sWt[(64 + 8 * kf + t4 + 4) * SW + 8 * nf + g];
            mma_tf32(acc[nf], a, b0, b1);
        }
    }

    int sa = wbase + g, sb = sa + 8;
    #pragma unroll
    for (int nf = 0; nf < NF; nf++) {
        int col = 8 * nf + 2 * t4;
        float v0 = acc[nf][0], v1 = acc[nf][1];
        float v2 = acc[nf][2], v3 = acc[nf][3];
        if (ACT == 1) {
            v0 = (v0 >= 0.f) ? v0 : NEG_SLOPE * v0;
            v1 = (v1 >= 0.f) ? v1 : NEG_SLOPE * v1;
            v2 = (v2 >= 0.f) ? v2 : NEG_SLOPE * v2;
            v3 = (v3 >= 0.f) ? v3 : NEG_SLOPE * v3;
        }
        if (sizeof(TY) == 2) {
            if (sa < N_NODES) {
                __half2 h = __floats2half2_rn(v0, v1);
                *(__half2*)((__half*)Y + (size_t)sa * DOUT + col) = h;
            }
            if (sb < N_NODES) {
                __half2 h = __floats2half2_rn(v2, v3);
                *(__half2*)((__half*)Y + (size_t)sb * DOUT + col) = h;
            }
        } else {
            if (sa < N_NODES) {
                float2 o; o.x = v0; o.y = v1;
                *(float2*)((float*)Y + (size_t)sa * DOUT + col) = o;
            }
            if (sb < N_NODES) {
                float2 o; o.x = v2; o.y = v3;
                *(float2*)((float*)Y + (size_t)sb * DOUT + col) = o;
            }
        }
    }
}

template <int DOUT, int SW>
__device__ __forceinline__ void stage_w2_tf32(
        const float* __restrict__ Ws, const float* __restrict__ Wn,
        const float* __restrict__ b, unsigned* sWt, float* sbias) {
    int t = threadIdx.x;
    for (int i = t; i < F * DOUT; i += 256) {
        int k = i / DOUT, n = i % DOUT;
        sWt[k * SW + n]        = f2tf32(__ldg(&Ws[i]));
        sWt[(64 + k) * SW + n] = f2tf32(__ldg(&Wn[i]));
    }
    if (t < DOUT) sbias[t] = b[t];
}

template <int DOUT, int ACT, int SW, typename TX, typename TY>
__global__ __launch_bounds__(256) void gemm_out_kernel(
        const TX* __restrict__ X, const __half* __restrict__ PL,
        const float* __restrict__ Ws, const float* __restrict__ Wn,
        const float* __restrict__ b, TY* __restrict__ Y) {
    __shared__ unsigned sWt[128 * SW];
    __shared__ float sbias[DOUT];
    stage_w2_tf32<DOUT, SW>(Ws, Wn, b, sWt, sbias);
    __syncthreads();
    gemm_out_tf32_body<DOUT, ACT, SW>(X, PL, sWt, sbias, Y, blockIdx.x * 128);
}

// ---------------- launch -----------------------------------------------------
extern "C" void kernel_launch(void* const* d_in, const int* in_sizes, int n_in,
                              void* d_out, int out_size) {
    const float* in_feat = (const float*)d_in[0];
    const int*   src     = (const int*)d_in[1];
    const int*   dst     = (const int*)d_in[2];
    const float* W_pool1 = (const float*)d_in[3];
    const float* b_pool1 = (const float*)d_in[4];
    const float* W_self1 = (const float*)d_in[5];
    const float* W_neigh1= (const float*)d_in[6];
    const float* bias1   = (const float*)d_in[7];
    const float* W_pool2 = (const float*)d_in[8];
    const float* b_pool2 = (const float*)d_in[9];
    const float* W_self2 = (const float*)d_in[10];
    const float* W_neigh2= (const float*)d_in[11];
    const float* bias2   = (const float*)d_in[12];
    float* out = (float*)d_out;

    __half *dP, *dPl, *dH;
    cudaGetSymbolAddress((void**)&dP, g_P);
    cudaGetSymbolAddress((void**)&dPl, g_Pl);
    cudaGetSymbolAddress((void**)&dH, g_H);

    const int POOL_WARPS = (N_NODES + 3) / 4;
    const int POOLB = (POOL_WARPS * 32 + 255) / 256;

    // K1: flag reset + rank-recording histogram + layer-1 pool GEMM (tf32)
    hist_gemm_kernel<<<EB4 + NB128, 256>>>((const int4*)dst,
                                           in_feat, W_pool1, b_pool1, dP);
    // K2: single-pass scan (offsets only)
    scan_kernel<<<SCAN_NB, SCAN_BLK>>>();
    // K3: atomic-free CSR fill (premultiplied entries)
    fill_csr_kernel<<<EB4, 256>>>((const int4*)src, (const int4*)dst);
    // K4: layer-1 pool
    pool_kernel<<<POOLB, 256>>>(dP, dPl);
    // K5: H(fp16) = leaky(X@Ws1 + Pl@Wn1 + b1)  (tf32, K=128)
    gemm_out_kernel<64, 1, 72><<<NB128, 256>>>(in_feat, dPl, W_self1, W_neigh1,
                                               bias1, dH);
    // K6: P = relu(H@Wp2 + bp2)  (tf32, fp16 input)
    gemm_pool_kernel<<<NB128, 256>>>(dH, W_pool2, b_pool2, dP);
    // K7: layer-2 pool
    pool_kernel<<<POOLB, 256>>>(dP, dPl);
    // K8: out(fp32) = H@Ws2 + Pl@Wn2 + b2  (tf32, K=128, fp16 input)
    gemm_out_kernel<16, 0, 24><<<NB128, 256>>>(dH, dPl, W_self2, W_neigh2,
                                               bias2, out);
}